// round 15
// baseline (speedup 1.0000x reference)
#include <cuda_runtime.h>
#include <cuda_fp16.h>
#include <cstdint>

#define D_FEAT    64
#define MAX_NODES 50000
#define MAX_EDGES 800000

// Scratch (__device__ globals — no allocation allowed).
static __device__ __half g_y[(size_t)MAX_NODES * D_FEAT];     // relu(x W + b), fp16
static __device__ __half g_hout[(size_t)MAX_NODES * D_FEAT];  // fp16 accumulator
static __device__ int    g_is64;                              // edge_index dtype flag

// ---------------------------------------------------------------------------
// Setup: block 0 detects index dtype (int64 indices < 2^31 have every odd
// 32-bit word == 0); all blocks zero the fp16 accumulator (4 uint4 / thread).
// ---------------------------------------------------------------------------
__global__ __launch_bounds__(256) void setup_kernel(const int* __restrict__ ei_words,
                                                    int n16) {
    if (blockIdx.x == 0) {
        __shared__ int any_nonzero;
        if (threadIdx.x == 0) any_nonzero = 0;
        __syncthreads();
        if (ei_words[2 * threadIdx.x + 1] != 0) atomicOr(&any_nonzero, 1);
        __syncthreads();
        if (threadIdx.x == 0) g_is64 = any_nonzero ? 0 : 1;
    }
    int t = blockIdx.x * blockDim.x + threadIdx.x;
    uint4 z = make_uint4(0u, 0u, 0u, 0u);
#pragma unroll
    for (int j = 0; j < 4; j++) {
        int i = t * 4 + j;
        if (i < n16) ((uint4*)g_hout)[i] = z;
    }
}

// ---------------------------------------------------------------------------
// Per-node MLP: y = relu(x @ W + b), stored fp16.  (R11-proven version.)
// W pair-major in smem (sWp[k2][2c+parity]) + padded x tile; math is
// fma.rn.f32x2 on (even-k, odd-k) partial pairs.
// Thread owns rows {r0+16j}, cols {c4+16cc}.
// ---------------------------------------------------------------------------
__global__ __launch_bounds__(256) void mlp_kernel(const float* __restrict__ x,
                                                  const float* __restrict__ W,
                                                  const float* __restrict__ b,
                                                  int n) {
    __shared__ float sWp[32 * 128];   // [k2][2c+par], 16KB
    __shared__ float sx[64 * 68];     // [r][k], padded stride, 17KB

    const int tid  = threadIdx.x;
    const int row0 = blockIdx.x * 64;

    // Fill sWp: W[k][c] -> sWp[k>>1][2c + (k&1)]
#pragma unroll
    for (int i = 0; i < 4; i++) {
        int idx = tid + 256 * i;          // 0..1023 over W's float4s
        int k   = idx >> 4;
        int kk  = idx & 15;
        float4 v = ((const float4*)W)[idx];
        float* dstrow = &sWp[(k >> 1) * 128 + (k & 1)];
        dstrow[2 * (4 * kk + 0)] = v.x;
        dstrow[2 * (4 * kk + 1)] = v.y;
        dstrow[2 * (4 * kk + 2)] = v.z;
        dstrow[2 * (4 * kk + 3)] = v.w;
    }
    // Fill sx
#pragma unroll
    for (int i = 0; i < 4; i++) {
        int idx = tid + 256 * i;
        int r   = idx >> 4;
        int kk  = idx & 15;
        float4 v = make_float4(0.f, 0.f, 0.f, 0.f);
        if (row0 + r < n)
            v = ((const float4*)(x + (size_t)(row0 + r) * D_FEAT))[kk];
        *(float4*)&sx[r * 68 + kk * 4] = v;
    }
    __syncthreads();

    const int c4 = tid & 15;   // cols c4 + 16*cc
    const int r0 = tid >> 4;   // rows r0 + 16*j

    unsigned long long acc[4][4];
#pragma unroll
    for (int j = 0; j < 4; j++)
#pragma unroll
        for (int cc = 0; cc < 4; cc++) acc[j][cc] = 0ULL;

#pragma unroll 4
    for (int k4 = 0; k4 < 16; k4++) {
        // x: 4 rows, each LDS.128 = two f32x2 pairs
        ulonglong2 xr[4];
#pragma unroll
        for (int j = 0; j < 4; j++)
            xr[j] = *(const ulonglong2*)&sx[(r0 + 16 * j) * 68 + k4 * 4];

#pragma unroll
        for (int sub = 0; sub < 2; sub++) {
            int k2 = k4 * 2 + sub;
            unsigned long long wp[4];
#pragma unroll
            for (int cc = 0; cc < 4; cc++)
                wp[cc] = *(const unsigned long long*)
                         &sWp[k2 * 128 + 2 * (c4 + 16 * cc)];
#pragma unroll
            for (int j = 0; j < 4; j++) {
                unsigned long long xp = sub ? xr[j].y : xr[j].x;
#pragma unroll
                for (int cc = 0; cc < 4; cc++)
                    asm("fma.rn.f32x2 %0, %1, %2, %0;"
                        : "+l"(acc[j][cc]) : "l"(xp), "l"(wp[cc]));
            }
        }
    }

    // Fold pairs, add bias, relu; stage fp32 results into sx (16B-aligned rows).
    float bv[4];
#pragma unroll
    for (int cc = 0; cc < 4; cc++) bv[cc] = __ldg(&b[c4 + 16 * cc]);

    __syncthreads();   // done reading sx; reuse as staging
#pragma unroll
    for (int j = 0; j < 4; j++) {
#pragma unroll
        for (int cc = 0; cc < 4; cc++) {
            unsigned long long a = acc[j][cc];
            float lo = __uint_as_float((unsigned)(a & 0xFFFFFFFFu));
            float hi = __uint_as_float((unsigned)(a >> 32));
            float s  = fmaxf(lo + hi + bv[cc], 0.f);
            sx[(r0 + 16 * j) * 68 + (c4 + 16 * cc)] = s;
        }
    }
    __syncthreads();

    // Coalesced fp16 store.
#pragma unroll
    for (int i = 0; i < 4; i++) {
        int idx = tid + 256 * i;
        int r   = idx >> 4;
        int kk  = idx & 15;
        if (row0 + r < n) {
            float4 v = *(const float4*)&sx[r * 68 + kk * 4];
            __half2 h0 = __floats2half2_rn(v.x, v.y);
            __half2 h1 = __floats2half2_rn(v.z, v.w);
            uint2 pk;
            pk.x = *(const unsigned*)&h0;
            pk.y = *(const unsigned*)&h1;
            ((uint2*)(g_y + (size_t)(row0 + r) * D_FEAT))[kk] = pk;
        }
    }
}

// ---------------------------------------------------------------------------
// Edge scatter: g_hout[dst] += y[src], all fp16, indices read directly from
// edge_index (uniform dtype branch; 8 lanes broadcast each index load).
// 8 lanes/edge (lane q <-> uint4 = 8 halves; warp = 4 rows x 128B coalesced),
// 4 independent edges/thread (MLP=4), red.v4.f16x2 covers 8 feats per op.
// At the measured L2 atomic-op floor.
// ---------------------------------------------------------------------------
__global__ __launch_bounds__(256) void scatter_kernel(const void* __restrict__ ei,
                                                      int E, int EQ) {
    int t = blockIdx.x * blockDim.x + threadIdx.x;
    int e0 = t >> 3;
    if (e0 >= EQ) return;
    int q = t & 7;

    int e[4];
    bool valid[4];
#pragma unroll
    for (int j = 0; j < 4; j++) {
        e[j] = e0 + j * EQ;
        valid[j] = (e[j] < E);
        if (!valid[j]) e[j] = 0;
    }

    int src[4], dst[4];
    if (g_is64) {
        const long long* p = (const long long*)ei;
#pragma unroll
        for (int j = 0; j < 4; j++) src[j] = (int)__ldg(&p[e[j]]);
#pragma unroll
        for (int j = 0; j < 4; j++) dst[j] = (int)__ldg(&p[(size_t)E + e[j]]);
    } else {
        const int* p = (const int*)ei;
#pragma unroll
        for (int j = 0; j < 4; j++) src[j] = __ldg(&p[e[j]]);
#pragma unroll
        for (int j = 0; j < 4; j++) dst[j] = __ldg(&p[(size_t)E + e[j]]);
    }

    uint4 hv[4];
#pragma unroll
    for (int j = 0; j < 4; j++)
        hv[j] = __ldg((const uint4*)(g_y + (size_t)src[j] * D_FEAT) + q);

#pragma unroll
    for (int j = 0; j < 4; j++) {
        if (!valid[j]) continue;
        __half* o = g_hout + (size_t)dst[j] * D_FEAT + (q << 3);
        asm volatile("red.global.add.noftz.v4.f16x2 [%0], {%1, %2, %3, %4};"
                     :: "l"(o), "r"(hv[j].x), "r"(hv[j].y), "r"(hv[j].z), "r"(hv[j].w)
                     : "memory");
    }
}

// ---------------------------------------------------------------------------
// Convert fp16 accumulator -> fp32 output. 4 independent uint4 groups per
// thread (batched loads -> MLP=4), so the dependent load latency is ~4x
// better hidden than the 1-group version (was 7.7us, latency-bound).
// ---------------------------------------------------------------------------
__global__ __launch_bounds__(256) void convert_kernel(float* __restrict__ out,
                                                      int n16, int NQ) {
    int t = blockIdx.x * blockDim.x + threadIdx.x;
    if (t >= NQ) return;

    int idx[4];
    bool valid[4];
#pragma unroll
    for (int j = 0; j < 4; j++) {
        idx[j] = t + j * NQ;
        valid[j] = (idx[j] < n16);
        if (!valid[j]) idx[j] = 0;
    }

    uint4 h[4];
#pragma unroll
    for (int j = 0; j < 4; j++) h[j] = __ldg(((const uint4*)g_hout) + idx[j]);

#pragma unroll
    for (int j = 0; j < 4; j++) {
        if (!valid[j]) continue;
        float2 f0 = __half22float2(*(const __half2*)&h[j].x);
        float2 f1 = __half22float2(*(const __half2*)&h[j].y);
        float2 f2 = __half22float2(*(const __half2*)&h[j].z);
        float2 f3 = __half22float2(*(const __half2*)&h[j].w);
        float4* o = (float4*)out + (size_t)idx[j] * 2;
        o[0] = make_float4(f0.x, f0.y, f1.x, f1.y);
        o[1] = make_float4(f2.x, f2.y, f3.x, f3.y);
    }
}

// ---------------------------------------------------------------------------
// Inputs: x [n*64 f32], edge_index [2*E int32/int64], W [64*64 f32], b [64].
// ---------------------------------------------------------------------------
extern "C" void kernel_launch(void* const* d_in, const int* in_sizes, int n_in,
                              void* d_out, int out_size) {
    const float* x   = (const float*)d_in[0];
    const void*  ei  = d_in[1];
    const float* W   = (const float*)d_in[2];
    const float* b   = (const float*)d_in[3];
    float*       out = (float*)d_out;

    int n = in_sizes[0] / D_FEAT;
    int E = in_sizes[1] / 2;
    int n16 = n * D_FEAT / 8;   // uint4 groups in the fp16 accumulator

    int zthreads = (n16 + 3) / 4;
    setup_kernel<<<(zthreads + 255) / 256, 256>>>((const int*)ei, n16);

    mlp_kernel<<<(n + 63) / 64, 256>>>(x, W, b, n);

    int EQ = (E + 3) / 4;
    long long total = (long long)EQ * 8;
    int grid = (int)((total + 255) / 256);
    scatter_kernel<<<grid, 256>>>(ei, E, EQ);

    int NQ = (n16 + 3) / 4;
    convert_kernel<<<(NQ + 255) / 256, 256>>>(out, n16, NQ);
}

// round 16
// speedup vs baseline: 1.0447x; 1.0447x over previous
#include <cuda_runtime.h>
#include <cuda_fp16.h>
#include <cstdint>

#define D_FEAT    64
#define MAX_NODES 50000
#define MAX_EDGES 800000

// Scratch (__device__ globals — no allocation allowed).
static __device__ __half g_y[(size_t)MAX_NODES * D_FEAT];     // relu(x W + b), fp16
static __device__ __half g_hout[(size_t)MAX_NODES * D_FEAT];  // fp16 accumulator
static __device__ int    g_is64;                              // edge_index dtype flag

// ---------------------------------------------------------------------------
// Per-node MLP: y = relu(x @ W + b), stored fp16.  (R11-proven core.)
// Fused extras (replaces the old setup kernel):
//   - every block zeroes its 512-uint4 slice of g_hout (2 STG.128/thread,
//     fire-and-forget, issued before the FFMA mainloop),
//   - block 0 detects edge_index dtype (int64 < 2^31 => odd words all 0).
// W pair-major in smem (sWp[k2][2c+parity]); math is fma.rn.f32x2 on
// (even-k, odd-k) partial pairs. Thread owns rows {r0+16j}, cols {c4+16cc}.
// ---------------------------------------------------------------------------
__global__ __launch_bounds__(256) void mlp_kernel(const float* __restrict__ x,
                                                  const float* __restrict__ W,
                                                  const float* __restrict__ b,
                                                  const int* __restrict__ ei_words,
                                                  int n, int n16) {
    __shared__ float sWp[32 * 128];   // [k2][2c+par], 16KB
    __shared__ float sx[64 * 68];     // [r][k], padded stride, 17KB

    const int tid  = threadIdx.x;
    const int row0 = blockIdx.x * 64;

    // Zero this block's slice of the fp16 accumulator (coalesced, independent).
    {
        uint4 z = make_uint4(0u, 0u, 0u, 0u);
#pragma unroll
        for (int i = 0; i < 2; i++) {
            int zi = blockIdx.x * 512 + i * 256 + tid;
            if (zi < n16) ((uint4*)g_hout)[zi] = z;
        }
    }
    // Dtype detect (block 0 only).
    if (blockIdx.x == 0) {
        __shared__ int any_nonzero;
        if (tid == 0) any_nonzero = 0;
        __syncthreads();
        if (ei_words[2 * tid + 1] != 0) atomicOr(&any_nonzero, 1);
        __syncthreads();
        if (tid == 0) g_is64 = any_nonzero ? 0 : 1;
    }

    // Fill sWp: W[k][c] -> sWp[k>>1][2c + (k&1)]
#pragma unroll
    for (int i = 0; i < 4; i++) {
        int idx = tid + 256 * i;          // 0..1023 over W's float4s
        int k   = idx >> 4;
        int kk  = idx & 15;
        float4 v = ((const float4*)W)[idx];
        float* dstrow = &sWp[(k >> 1) * 128 + (k & 1)];
        dstrow[2 * (4 * kk + 0)] = v.x;
        dstrow[2 * (4 * kk + 1)] = v.y;
        dstrow[2 * (4 * kk + 2)] = v.z;
        dstrow[2 * (4 * kk + 3)] = v.w;
    }
    // Fill sx
#pragma unroll
    for (int i = 0; i < 4; i++) {
        int idx = tid + 256 * i;
        int r   = idx >> 4;
        int kk  = idx & 15;
        float4 v = make_float4(0.f, 0.f, 0.f, 0.f);
        if (row0 + r < n)
            v = ((const float4*)(x + (size_t)(row0 + r) * D_FEAT))[kk];
        *(float4*)&sx[r * 68 + kk * 4] = v;
    }
    __syncthreads();

    const int c4 = tid & 15;   // cols c4 + 16*cc
    const int r0 = tid >> 4;   // rows r0 + 16*j

    unsigned long long acc[4][4];
#pragma unroll
    for (int j = 0; j < 4; j++)
#pragma unroll
        for (int cc = 0; cc < 4; cc++) acc[j][cc] = 0ULL;

#pragma unroll 4
    for (int k4 = 0; k4 < 16; k4++) {
        // x: 4 rows, each LDS.128 = two f32x2 pairs
        ulonglong2 xr[4];
#pragma unroll
        for (int j = 0; j < 4; j++)
            xr[j] = *(const ulonglong2*)&sx[(r0 + 16 * j) * 68 + k4 * 4];

#pragma unroll
        for (int sub = 0; sub < 2; sub++) {
            int k2 = k4 * 2 + sub;
            unsigned long long wp[4];
#pragma unroll
            for (int cc = 0; cc < 4; cc++)
                wp[cc] = *(const unsigned long long*)
                         &sWp[k2 * 128 + 2 * (c4 + 16 * cc)];
#pragma unroll
            for (int j = 0; j < 4; j++) {
                unsigned long long xp = sub ? xr[j].y : xr[j].x;
#pragma unroll
                for (int cc = 0; cc < 4; cc++)
                    asm("fma.rn.f32x2 %0, %1, %2, %0;"
                        : "+l"(acc[j][cc]) : "l"(xp), "l"(wp[cc]));
            }
        }
    }

    // Fold pairs, add bias, relu; stage fp32 results into sx (16B-aligned rows).
    float bv[4];
#pragma unroll
    for (int cc = 0; cc < 4; cc++) bv[cc] = __ldg(&b[c4 + 16 * cc]);

    __syncthreads();   // done reading sx; reuse as staging
#pragma unroll
    for (int j = 0; j < 4; j++) {
#pragma unroll
        for (int cc = 0; cc < 4; cc++) {
            unsigned long long a = acc[j][cc];
            float lo = __uint_as_float((unsigned)(a & 0xFFFFFFFFu));
            float hi = __uint_as_float((unsigned)(a >> 32));
            float s  = fmaxf(lo + hi + bv[cc], 0.f);
            sx[(r0 + 16 * j) * 68 + (c4 + 16 * cc)] = s;
        }
    }
    __syncthreads();

    // Coalesced fp16 store.
#pragma unroll
    for (int i = 0; i < 4; i++) {
        int idx = tid + 256 * i;
        int r   = idx >> 4;
        int kk  = idx & 15;
        if (row0 + r < n) {
            float4 v = *(const float4*)&sx[r * 68 + kk * 4];
            __half2 h0 = __floats2half2_rn(v.x, v.y);
            __half2 h1 = __floats2half2_rn(v.z, v.w);
            uint2 pk;
            pk.x = *(const unsigned*)&h0;
            pk.y = *(const unsigned*)&h1;
            ((uint2*)(g_y + (size_t)(row0 + r) * D_FEAT))[kk] = pk;
        }
    }
}

// ---------------------------------------------------------------------------
// Edge scatter: g_hout[dst] += y[src], all fp16, indices read directly from
// edge_index (uniform dtype branch; 8 lanes broadcast each index load).
// 8 lanes/edge (lane q <-> uint4 = 8 halves; warp = 4 rows x 128B coalesced),
// 4 independent edges/thread (MLP=4), red.v4.f16x2 covers 8 feats per op.
// At the measured L2 atomic-op floor (~19-22us for 6.4M REDs).
// ---------------------------------------------------------------------------
__global__ __launch_bounds__(256) void scatter_kernel(const void* __restrict__ ei,
                                                      int E, int EQ) {
    int t = blockIdx.x * blockDim.x + threadIdx.x;
    int e0 = t >> 3;
    if (e0 >= EQ) return;
    int q = t & 7;

    int e[4];
    bool valid[4];
#pragma unroll
    for (int j = 0; j < 4; j++) {
        e[j] = e0 + j * EQ;
        valid[j] = (e[j] < E);
        if (!valid[j]) e[j] = 0;
    }

    int src[4], dst[4];
    if (g_is64) {
        const long long* p = (const long long*)ei;
#pragma unroll
        for (int j = 0; j < 4; j++) src[j] = (int)__ldg(&p[e[j]]);
#pragma unroll
        for (int j = 0; j < 4; j++) dst[j] = (int)__ldg(&p[(size_t)E + e[j]]);
    } else {
        const int* p = (const int*)ei;
#pragma unroll
        for (int j = 0; j < 4; j++) src[j] = __ldg(&p[e[j]]);
#pragma unroll
        for (int j = 0; j < 4; j++) dst[j] = __ldg(&p[(size_t)E + e[j]]);
    }

    uint4 hv[4];
#pragma unroll
    for (int j = 0; j < 4; j++)
        hv[j] = __ldg((const uint4*)(g_y + (size_t)src[j] * D_FEAT) + q);

#pragma unroll
    for (int j = 0; j < 4; j++) {
        if (!valid[j]) continue;
        __half* o = g_hout + (size_t)dst[j] * D_FEAT + (q << 3);
        asm volatile("red.global.add.noftz.v4.f16x2 [%0], {%1, %2, %3, %4};"
                     :: "l"(o), "r"(hv[j].x), "r"(hv[j].y), "r"(hv[j].z), "r"(hv[j].w)
                     : "memory");
    }
}

// ---------------------------------------------------------------------------
// Convert fp16 accumulator -> fp32 output. One thread per uint4 (R14-proven:
// high TLP beats per-thread ILP for this short streaming kernel).
// ---------------------------------------------------------------------------
__global__ __launch_bounds__(256) void convert_kernel(float* __restrict__ out, int n16) {
    int i = blockIdx.x * blockDim.x + threadIdx.x;
    if (i >= n16) return;
    uint4 h = ((const uint4*)g_hout)[i];
    float2 f0 = __half22float2(*(const __half2*)&h.x);
    float2 f1 = __half22float2(*(const __half2*)&h.y);
    float2 f2 = __half22float2(*(const __half2*)&h.z);
    float2 f3 = __half22float2(*(const __half2*)&h.w);
    float4* o = (float4*)out + (size_t)i * 2;
    o[0] = make_float4(f0.x, f0.y, f1.x, f1.y);
    o[1] = make_float4(f2.x, f2.y, f3.x, f3.y);
}

// ---------------------------------------------------------------------------
// Inputs: x [n*64 f32], edge_index [2*E int32/int64], W [64*64 f32], b [64].
// ---------------------------------------------------------------------------
extern "C" void kernel_launch(void* const* d_in, const int* in_sizes, int n_in,
                              void* d_out, int out_size) {
    const float* x   = (const float*)d_in[0];
    const void*  ei  = d_in[1];
    const float* W   = (const float*)d_in[2];
    const float* b   = (const float*)d_in[3];
    float*       out = (float*)d_out;

    int n = in_sizes[0] / D_FEAT;
    int E = in_sizes[1] / 2;
    int n16 = n * D_FEAT / 8;   // uint4 groups in the fp16 accumulator

    // mlp also zeroes g_hout (512 uint4/block covers n16 exactly) and
    // detects the index dtype in block 0.
    mlp_kernel<<<(n + 63) / 64, 256>>>(x, W, b, (const int*)ei, n, n16);

    int EQ = (E + 3) / 4;
    long long total = (long long)EQ * 8;
    int grid = (int)((total + 255) / 256);
    scatter_kernel<<<grid, 256>>>(ei, E, EQ);

    convert_kernel<<<(n16 + 255) / 256, 256>>>(out, n16);
}

// round 17
// speedup vs baseline: 1.2622x; 1.2082x over previous
#include <cuda_runtime.h>
#include <cuda_fp16.h>
#include <cstdint>

#define D_FEAT    64
#define MAX_NODES 50000
#define MAX_EDGES 800000

// Scratch (__device__ globals — no allocation allowed).
static __device__ __half g_y[(size_t)MAX_NODES * D_FEAT];     // relu(x W + b), fp16
static __device__ __half g_hout[(size_t)MAX_NODES * D_FEAT];  // fp16 accumulator
static __device__ int    g_is64;                              // edge_index dtype flag

__device__ __forceinline__ unsigned f2tf32(float v) {
    unsigned r;
    asm("cvt.rna.tf32.f32 %0, %1;" : "=r"(r) : "f"(v));
    return r;
}

// ---------------------------------------------------------------------------
// Per-node MLP via TF32 tensor cores: y = relu(x @ W + b), stored fp16.
// Block: 256 thr / 64 rows. Warp w: rows (w&3)*16..+16, cols (w>>2)*32..+32.
// mma.sync.m16n8k8 tf32: per warp 32 A-frag LDS + 64 B-frag LDS + 32 MMA.
// TF32 conversion done once per element during smem fill.
// Fused: per-block g_hout zeroing + (block 0) edge dtype detection.
// ---------------------------------------------------------------------------
__global__ __launch_bounds__(256) void mlp_kernel(const float* __restrict__ x,
                                                  const float* __restrict__ W,
                                                  const float* __restrict__ b,
                                                  const int* __restrict__ ei_words,
                                                  int n, int n16) {
    __shared__ float sx[64 * 68];    // x tile (tf32-rounded), stride 68: A-frag
                                     // LDS conflict-free; reused as epilogue staging
    __shared__ float sWb[64 * 68];   // W (tf32-rounded), [k][c], stride 68

    const int tid  = threadIdx.x;
    const int row0 = blockIdx.x * 64;

    // Zero this block's slice of the fp16 accumulator (fire-and-forget).
    {
        uint4 z = make_uint4(0u, 0u, 0u, 0u);
#pragma unroll
        for (int i = 0; i < 2; i++) {
            int zi = blockIdx.x * 512 + i * 256 + tid;
            if (zi < n16) ((uint4*)g_hout)[zi] = z;
        }
    }
    // Dtype detect (block 0 only): int64 idx < 2^31 => odd 32-bit words all 0.
    if (blockIdx.x == 0) {
        __shared__ int any_nonzero;
        if (tid == 0) any_nonzero = 0;
        __syncthreads();
        if (ei_words[2 * tid + 1] != 0) atomicOr(&any_nonzero, 1);
        __syncthreads();
        if (tid == 0) g_is64 = any_nonzero ? 0 : 1;
    }

    // Fill sWb (tf32-rounded W).
#pragma unroll
    for (int i = 0; i < 4; i++) {
        int idx = tid + 256 * i;          // float4 index over W
        int k   = idx >> 4;
        int kk  = idx & 15;
        float4 v = ((const float4*)W)[idx];
        float* d = &sWb[k * 68 + kk * 4];
        d[0] = __uint_as_float(f2tf32(v.x));
        d[1] = __uint_as_float(f2tf32(v.y));
        d[2] = __uint_as_float(f2tf32(v.z));
        d[3] = __uint_as_float(f2tf32(v.w));
    }
    // Fill sx (tf32-rounded x tile; zero-padded rows past n).
#pragma unroll
    for (int i = 0; i < 4; i++) {
        int idx = tid + 256 * i;
        int r   = idx >> 4;
        int kk  = idx & 15;
        float4 v = make_float4(0.f, 0.f, 0.f, 0.f);
        if (row0 + r < n)
            v = ((const float4*)(x + (size_t)(row0 + r) * D_FEAT))[kk];
        float* d = &sx[r * 68 + kk * 4];
        d[0] = __uint_as_float(f2tf32(v.x));
        d[1] = __uint_as_float(f2tf32(v.y));
        d[2] = __uint_as_float(f2tf32(v.z));
        d[3] = __uint_as_float(f2tf32(v.w));
    }
    __syncthreads();

    const int warp = tid >> 5;
    const int lane = tid & 31;
    const int gid  = lane >> 2;      // 0..7
    const int tig  = lane & 3;       // 0..3
    const int rbase = (warp & 3) * 16;
    const int nbase = (warp >> 2) * 32;

    // Preload A fragments for all 8 k-steps.
    unsigned a[8][4];
#pragma unroll
    for (int s = 0; s < 8; s++) {
        int k0 = s * 8;
        a[s][0] = __float_as_uint(sx[(rbase + gid)     * 68 + k0 + tig]);
        a[s][1] = __float_as_uint(sx[(rbase + gid + 8) * 68 + k0 + tig]);
        a[s][2] = __float_as_uint(sx[(rbase + gid)     * 68 + k0 + tig + 4]);
        a[s][3] = __float_as_uint(sx[(rbase + gid + 8) * 68 + k0 + tig + 4]);
    }

    float c[4][4];
#pragma unroll
    for (int nt = 0; nt < 4; nt++)
#pragma unroll
        for (int i = 0; i < 4; i++) c[nt][i] = 0.f;

#pragma unroll
    for (int nt = 0; nt < 4; nt++) {
        int n0 = nbase + nt * 8;
#pragma unroll
        for (int s = 0; s < 8; s++) {
            int k0 = s * 8;
            unsigned b0 = __float_as_uint(sWb[(k0 + tig)     * 68 + n0 + gid]);
            unsigned b1 = __float_as_uint(sWb[(k0 + tig + 4) * 68 + n0 + gid]);
            asm("mma.sync.aligned.m16n8k8.row.col.f32.tf32.tf32.f32 "
                "{%0,%1,%2,%3}, {%4,%5,%6,%7}, {%8,%9}, {%0,%1,%2,%3};"
                : "+f"(c[nt][0]), "+f"(c[nt][1]), "+f"(c[nt][2]), "+f"(c[nt][3])
                : "r"(a[s][0]), "r"(a[s][1]), "r"(a[s][2]), "r"(a[s][3]),
                  "r"(b0), "r"(b1));
        }
    }

    // Stage raw accumulators into sx: C[gid(+8)][n0+2tig(+1)].
    __syncthreads();   // done reading sx as A source
#pragma unroll
    for (int nt = 0; nt < 4; nt++) {
        int n0 = nbase + nt * 8;
        sx[(rbase + gid)     * 68 + n0 + 2 * tig]     = c[nt][0];
        sx[(rbase + gid)     * 68 + n0 + 2 * tig + 1] = c[nt][1];
        sx[(rbase + gid + 8) * 68 + n0 + 2 * tig]     = c[nt][2];
        sx[(rbase + gid + 8) * 68 + n0 + 2 * tig + 1] = c[nt][3];
    }
    __syncthreads();

    // Bias + relu + coalesced fp16 store.
#pragma unroll
    for (int i = 0; i < 4; i++) {
        int idx = tid + 256 * i;
        int r   = idx >> 4;
        int kk  = idx & 15;
        if (row0 + r < n) {
            float4 v  = *(const float4*)&sx[r * 68 + kk * 4];
            float4 bb = __ldg((const float4*)b + kk);
            __half2 h0 = __floats2half2_rn(fmaxf(v.x + bb.x, 0.f),
                                           fmaxf(v.y + bb.y, 0.f));
            __half2 h1 = __floats2half2_rn(fmaxf(v.z + bb.z, 0.f),
                                           fmaxf(v.w + bb.w, 0.f));
            uint2 pk;
            pk.x = *(const unsigned*)&h0;
            pk.y = *(const unsigned*)&h1;
            ((uint2*)(g_y + (size_t)(row0 + r) * D_FEAT))[kk] = pk;
        }
    }
}

// ---------------------------------------------------------------------------
// Edge scatter: g_hout[dst] += y[src], all fp16, indices read directly from
// edge_index (uniform dtype branch; 8 lanes broadcast each index load).
// 8 lanes/edge (lane q <-> uint4 = 8 halves; warp = 4 rows x 128B coalesced),
// 4 independent edges/thread (MLP=4), red.v4.f16x2 covers 8 feats per op.
// At the measured L2 atomic-op floor (~19-22us for 6.4M REDs).
// ---------------------------------------------------------------------------
__global__ __launch_bounds__(256) void scatter_kernel(const void* __restrict__ ei,
                                                      int E, int EQ) {
    int t = blockIdx.x * blockDim.x + threadIdx.x;
    int e0 = t >> 3;
    if (e0 >= EQ) return;
    int q = t & 7;

    int e[4];
    bool valid[4];
#pragma unroll
    for (int j = 0; j < 4; j++) {
        e[j] = e0 + j * EQ;
        valid[j] = (e[j] < E);
        if (!valid[j]) e[j] = 0;
    }

    int src[4], dst[4];
    if (g_is64) {
        const long long* p = (const long long*)ei;
#pragma unroll
        for (int j = 0; j < 4; j++) src[j] = (int)__ldg(&p[e[j]]);
#pragma unroll
        for (int j = 0; j < 4; j++) dst[j] = (int)__ldg(&p[(size_t)E + e[j]]);
    } else {
        const int* p = (const int*)ei;
#pragma unroll
        for (int j = 0; j < 4; j++) src[j] = __ldg(&p[e[j]]);
#pragma unroll
        for (int j = 0; j < 4; j++) dst[j] = __ldg(&p[(size_t)E + e[j]]);
    }

    uint4 hv[4];
#pragma unroll
    for (int j = 0; j < 4; j++)
        hv[j] = __ldg((const uint4*)(g_y + (size_t)src[j] * D_FEAT) + q);

#pragma unroll
    for (int j = 0; j < 4; j++) {
        if (!valid[j]) continue;
        __half* o = g_hout + (size_t)dst[j] * D_FEAT + (q << 3);
        asm volatile("red.global.add.noftz.v4.f16x2 [%0], {%1, %2, %3, %4};"
                     :: "l"(o), "r"(hv[j].x), "r"(hv[j].y), "r"(hv[j].z), "r"(hv[j].w)
                     : "memory");
    }
}

// ---------------------------------------------------------------------------
// Convert fp16 accumulator -> fp32 output. One thread per uint4 (R14-proven:
// high TLP beats per-thread ILP for this short streaming kernel).
// ---------------------------------------------------------------------------
__global__ __launch_bounds__(256) void convert_kernel(float* __restrict__ out, int n16) {
    int i = blockIdx.x * blockDim.x + threadIdx.x;
    if (i >= n16) return;
    uint4 h = ((const uint4*)g_hout)[i];
    float2 f0 = __half22float2(*(const __half2*)&h.x);
    float2 f1 = __half22float2(*(const __half2*)&h.y);
    float2 f2 = __half22float2(*(const __half2*)&h.z);
    float2 f3 = __half22float2(*(const __half2*)&h.w);
    float4* o = (float4*)out + (size_t)i * 2;
    o[0] = make_float4(f0.x, f0.y, f1.x, f1.y);
    o[1] = make_float4(f2.x, f2.y, f3.x, f3.y);
}

// ---------------------------------------------------------------------------
// Inputs: x [n*64 f32], edge_index [2*E int32/int64], W [64*64 f32], b [64].
// ---------------------------------------------------------------------------
extern "C" void kernel_launch(void* const* d_in, const int* in_sizes, int n_in,
                              void* d_out, int out_size) {
    const float* x   = (const float*)d_in[0];
    const void*  ei  = d_in[1];
    const float* W   = (const float*)d_in[2];
    const float* b   = (const float*)d_in[3];
    float*       out = (float*)d_out;

    int n = in_sizes[0] / D_FEAT;
    int E = in_sizes[1] / 2;
    int n16 = n * D_FEAT / 8;   // uint4 groups in the fp16 accumulator

    // mlp also zeroes g_hout and detects the index dtype in block 0.
    mlp_kernel<<<(n + 63) / 64, 256>>>(x, W, b, (const int*)ei, n, n16);

    int EQ = (E + 3) / 4;
    long long total = (long long)EQ * 8;
    int grid = (int)((total + 255) / 256);
    scatter_kernel<<<grid, 256>>>(ei, E, EQ);

    convert_kernel<<<(n16 + 255) / 256, 256>>>(out, n16);
}